// round 17
// baseline (speedup 1.0000x reference)
#include <cuda_runtime.h>
#include <cuda_fp16.h>
#include <cstdint>
#include <math.h>

#define HIDDEN   2048
#define HEADS    16
#define HEAD_DIM 128
#define KV_RANK  256
#define ATTN_DIM 2048
#define BATCH    2
#define SEQ      2048
#define M_ROWS   (BATCH * SEQ)   // 4096

// ---------------- scratch (device globals; allocation-free) ----------------
__device__ float g_lat[M_ROWS * KV_RANK];

__device__ __half g_xh [M_ROWS * HIDDEN];
__device__ __half g_lath[M_ROWS * KV_RANK];
__device__ __half g_aoh[M_ROWS * ATTN_DIM];
__device__ __half g_qh [M_ROWS * ATTN_DIM], g_ql [M_ROWS * ATTN_DIM];
__device__ __half g_k1 [M_ROWS * ATTN_DIM];
__device__ __half g_vrm[M_ROWS * ATTN_DIM];                  // V row-major fp16
__device__ __half g_vt [BATCH * HEADS * HEAD_DIM * SEQ];     // V transposed
// weights transposed to [N,K] K-major, single fp16
__device__ __half g_WT1 [(ATTN_DIM + KV_RANK) * HIDDEN];     // [Wq ; Wkv_down] rows
__device__ __half g_WkuT[2 * ATTN_DIM * KV_RANK];
__device__ __half g_WoT [HIDDEN * ATTN_DIM];

// ======================= PTX helpers (baseline ISA) ========================
__device__ __forceinline__ uint32_t smem_u32(const void* p) {
    uint32_t a;
    asm("{ .reg .u64 t; cvta.to.shared.u64 t, %1; cvt.u32.u64 %0, t; }" : "=r"(a) : "l"(p));
    return a;
}
#define CP_ASYNC16(dst, src) \
    asm volatile("cp.async.cg.shared.global [%0], [%1], 16;" :: "r"(dst), "l"(src) : "memory")
#define CP_COMMIT() asm volatile("cp.async.commit_group;" ::: "memory")
#define CP_WAIT(n)  asm volatile("cp.async.wait_group %0;" :: "n"(n) : "memory")

#define LDSM4(r0, r1, r2, r3, a) \
    asm volatile("ldmatrix.sync.aligned.m8n8.x4.shared.b16 {%0,%1,%2,%3}, [%4];" \
        : "=r"(r0), "=r"(r1), "=r"(r2), "=r"(r3) : "r"(a))

__device__ __forceinline__ void mma16816(float* c, const uint32_t* a, const uint32_t* b) {
    asm volatile("mma.sync.aligned.m16n8k16.row.col.f32.f16.f16.f32 "
        "{%0,%1,%2,%3}, {%4,%5,%6,%7}, {%8,%9}, {%0,%1,%2,%3};"
        : "+f"(c[0]), "+f"(c[1]), "+f"(c[2]), "+f"(c[3])
        : "r"(a[0]), "r"(a[1]), "r"(a[2]), "r"(a[3]), "r"(b[0]), "r"(b[1]));
}
__device__ __forceinline__ uint32_t pack_hf2(float a, float b) {
    __half2 t = __floats2half2_rn(a, b);
    return *(uint32_t*)&t;
}
__device__ __forceinline__ void split2(float a, float b, __half2& h, __half2& l) {
    __half ha = __float2half_rn(a), hb = __float2half_rn(b);
    h = __halves2half2(ha, hb);
    l = __floats2half2_rn(a - __half2float(ha), b - __half2float(hb));
}

// ======================= conversion kernels ================================
// fp32 -> fp16 single
__global__ __launch_bounds__(256) void conv_h(const float4* __restrict__ in,
                                              __half* __restrict__ h, int n4)
{
    int i = blockIdx.x * blockDim.x + threadIdx.x;
    if (i >= n4) return;
    float4 x = in[i];
    ((__half2*)h)[i * 2 + 0] = __floats2half2_rn(x.x, x.y);
    ((__half2*)h)[i * 2 + 1] = __floats2half2_rn(x.z, x.w);
}

// fp16 V row-major -> transposed: VT[(b*2048 + hd) * 2048 + s]
__global__ __launch_bounds__(256) void conv_vt_h(const __half* __restrict__ V,
                                                 __half* __restrict__ T)
{
    __shared__ __half t[32][40];
    const int s0  = blockIdx.x * 32;
    const int hd0 = blockIdx.y * 32;
    const int b   = blockIdx.z;
    const int tid = threadIdx.x;
    for (int i = tid; i < 1024; i += 256) {
        int ss = i >> 5, dd = i & 31;
        t[ss][dd] = V[(size_t)(b * SEQ + s0 + ss) * 2048 + hd0 + dd];
    }
    __syncthreads();
    for (int i = tid; i < 512; i += 256) {
        int dd = i >> 4, sp = (i & 15) * 2;
        size_t o = (size_t)(b * 2048 + hd0 + dd) * 2048 + s0 + sp;
        *(__half2*)&T[o] = __halves2half2(t[sp][dd], t[sp + 1][dd]);
    }
}

// W [K,N] fp32 -> T [N,K] single fp16 (K-major). 32k x 128n tiles, vectorized.
__global__ __launch_bounds__(256) void conv_wt_T(const float* __restrict__ W,
                                                 __half* __restrict__ Th,
                                                 int K, int N)
{
    __shared__ float t[32][129];
    const int n0 = blockIdx.x * 128, k0 = blockIdx.y * 32;
    const int tid = threadIdx.x;
#pragma unroll
    for (int i = 0; i < 4; ++i) {
        int idx = tid + i * 256;
        int r = idx >> 5, c4 = (idx & 31) * 4;
        float4 v = *(const float4*)&W[(size_t)(k0 + r) * N + n0 + c4];
        t[r][c4 + 0] = v.x; t[r][c4 + 1] = v.y;
        t[r][c4 + 2] = v.z; t[r][c4 + 3] = v.w;
    }
    __syncthreads();
#pragma unroll
    for (int i = 0; i < 2; ++i) {
        int idx = tid + i * 256;
        int n = idx >> 2, kh = (idx & 3) * 8;
        uint4 u;
        uint32_t* up = (uint32_t*)&u;
#pragma unroll
        for (int j = 0; j < 4; ++j) {
            __half2 o = __floats2half2_rn(t[kh + 2 * j][n], t[kh + 2 * j + 1][n]);
            up[j] = *(uint32_t*)&o;
        }
        *(uint4*)&Th[(size_t)(n0 + n) * K + k0 + kh] = u;
    }
}

// ======================= mma.sync fp16 GEMM (ldmatrix) =====================
template<int MODE, bool SPLITA>
__global__ __launch_bounds__(256, 2) void gemm_mma(
    const __half* __restrict__ Ah, const __half* __restrict__ Al,
    const __half* __restrict__ Bw,
    float* __restrict__ Cf, __half* __restrict__ Oh, __half* __restrict__ Ol,
    __half* __restrict__ O2,
    int M, int N, int K, float sc)
{
    constexpr int NMAT = SPLITA ? 3 : 2;
    constexpr uint32_t STAGE = NMAT * 10240;

    extern __shared__ char smem[];
    const uint32_t sbase = smem_u32(smem);
    const int tid  = threadIdx.x;
    const int lane = tid & 31;
    const int w    = tid >> 5;
    const int bm = blockIdx.y * 128;
    const int bn = blockIdx.x * 128;
    const int wm = (w & 3) * 32;
    const int wn = (w >> 2) * 64;
    const int qr = lane >> 2;
    const int qc = lane & 3;

    const __half* srcs[3] = { Ah, SPLITA ? Al : Bw, Bw };
    const int rowoff[3] = { bm, SPLITA ? bm : bn, bn };

    const uint32_t lm = (uint32_t)(lane & 15) * 80 + (uint32_t)(lane >> 4) * 16;

    float acc[2][8][4];
#pragma unroll
    for (int mf = 0; mf < 2; ++mf)
#pragma unroll
        for (int nf = 0; nf < 8; ++nf)
#pragma unroll
            for (int e = 0; e < 4; ++e) acc[mf][nf][e] = 0.f;

    const int NC = K >> 5;

    auto issue = [&](int c) {
        const uint32_t st = sbase + (c & 1) * STAGE;
        const int k0 = c << 5;
#pragma unroll
        for (int i = 0; i < 2 * NMAT; ++i) {
            const int mat = i >> 1;
            const int sub = ((i & 1) << 8) + tid;
            const int r = sub >> 2, v = sub & 3;
            const void* g = srcs[mat] + (size_t)(rowoff[mat] + r) * K + k0 + v * 8;
            CP_ASYNC16(st + mat * 10240 + r * 80 + v * 16, g);
        }
        CP_COMMIT();
    };

    issue(0);

    for (int c = 0; c < NC; ++c) {
        if (c + 1 < NC) { issue(c + 1); CP_WAIT(1); }
        else            { CP_WAIT(0); }
        __syncthreads();

        const uint32_t st = sbase + (c & 1) * STAGE;
        const uint32_t aAh = st + wm * 80 + lm;
        const uint32_t aAl = st + 10240 + wm * 80 + lm;
        const uint32_t aB  = st + (NMAT - 1) * 10240 + wn * 80 + lm;

#pragma unroll
        for (int ks = 0; ks < 2; ++ks) {
            const uint32_t kb = ks * 32;
            uint32_t ah[2][4], al[2][4];
            LDSM4(ah[0][0], ah[0][1], ah[0][2], ah[0][3], aAh + kb);
            LDSM4(ah[1][0], ah[1][1], ah[1][2], ah[1][3], aAh + 16 * 80 + kb);
            if (SPLITA) {
                LDSM4(al[0][0], al[0][1], al[0][2], al[0][3], aAl + kb);
                LDSM4(al[1][0], al[1][1], al[1][2], al[1][3], aAl + 16 * 80 + kb);
            }
#pragma unroll
            for (int np = 0; np < 4; ++np) {
                uint32_t h0, h1, h2, h3;
                LDSM4(h0, h1, h2, h3, aB + (uint32_t)(np * 16) * 80 + kb);
                uint32_t be[2] = { h0, h2 }, bo[2] = { h1, h3 };
#pragma unroll
                for (int mf = 0; mf < 2; ++mf) {
                    mma16816(acc[mf][2 * np],     ah[mf], be);
                    mma16816(acc[mf][2 * np + 1], ah[mf], bo);
                    if (SPLITA) {
                        mma16816(acc[mf][2 * np],     al[mf], be);
                        mma16816(acc[mf][2 * np + 1], al[mf], bo);
                    }
                }
            }
        }
        __syncthreads();
    }

    // ---- epilogue ----
#pragma unroll
    for (int mf = 0; mf < 2; ++mf) {
        const int r0 = bm + wm + mf * 16 + qr;
        const int r1 = r0 + 8;
#pragma unroll
        for (int nf = 0; nf < 8; ++nf) {
            const int col = bn + wn + nf * 8 + qc * 2;
            float a0 = acc[mf][nf][0], a1 = acc[mf][nf][1];
            float a2 = acc[mf][nf][2], a3 = acc[mf][nf][3];
            if (MODE == 0) {
                *(float2*)&Cf[(size_t)r0 * N + col] = make_float2(a0, a1);
                *(float2*)&Cf[(size_t)r1 * N + col] = make_float2(a2, a3);
            } else if (MODE == 1) {
                if (col < 2048) {
                    a0 *= sc; a1 *= sc; a2 *= sc; a3 *= sc;
                    __half2 h, l;
                    split2(a0, a1, h, l);
                    *(__half2*)&Oh[(size_t)r0 * 2048 + col] = h;
                    *(__half2*)&Ol[(size_t)r0 * 2048 + col] = l;
                    split2(a2, a3, h, l);
                    *(__half2*)&Oh[(size_t)r1 * 2048 + col] = h;
                    *(__half2*)&Ol[(size_t)r1 * 2048 + col] = l;
                } else {
                    const int cl = col - 2048;
                    *(float2*)&Cf[(size_t)r0 * KV_RANK + cl] = make_float2(a0, a1);
                    *(float2*)&Cf[(size_t)r1 * KV_RANK + cl] = make_float2(a2, a3);
                }
            } else {   // MODE 2
                if (col < 2048) {
                    *(__half2*)&Oh[(size_t)r0 * 2048 + col] = __floats2half2_rn(a0, a1);
                    *(__half2*)&Oh[(size_t)r1 * 2048 + col] = __floats2half2_rn(a2, a3);
                } else {
                    const int cl = col - 2048;
                    *(__half2*)&O2[(size_t)r0 * 2048 + cl] = __floats2half2_rn(a0, a1);
                    *(__half2*)&O2[(size_t)r1 * 2048 + cl] = __floats2half2_rn(a2, a3);
                }
            }
        }
    }
}

// ---------------- RMSNorm over last dim (256) -> fp16 single ---------------
__global__ __launch_bounds__(256) void rmsnorm_kernel(
    const float* __restrict__ lat, const float* __restrict__ w,
    __half* __restrict__ lh)
{
    const int row = blockIdx.x;
    const int tid = threadIdx.x;
    float v = lat[(size_t)row * KV_RANK + tid];
    float ss = v * v;
#pragma unroll
    for (int o = 16; o; o >>= 1) ss += __shfl_xor_sync(0xffffffffu, ss, o);
    __shared__ float red[8];
    if ((tid & 31) == 0) red[tid >> 5] = ss;
    __syncthreads();
    float tot = red[0] + red[1] + red[2] + red[3] + red[4] + red[5] + red[6] + red[7];
    float r = rsqrtf(tot * (1.0f / KV_RANK) + 1e-6f);
    lh[(size_t)row * KV_RANK + tid] = __float2half_rn(w[tid] * v * r);
}

// ============ tensor-core flash attention (Q-tile 64, 2 CTAs/SM) ===========
// Scores arrive in log2 domain (Q prescaled by log2(e)/sqrt(d)); softmax via exp2f.
// 128 threads, 4 warps. smem: Qh@0 Ql@17408, 2 stages @34816/+35840. 2 CTAs/SM.
#define ATT_SMEM 106496
__global__ __launch_bounds__(128, 2) void attn_mma(
    const __half* __restrict__ Qh, const __half* __restrict__ Ql,
    const __half* __restrict__ Kg, const __half* __restrict__ VT,
    __half* __restrict__ Ohg)
{
    extern __shared__ char smA[];
    const uint32_t sb = smem_u32(smA);
    const int tid = threadIdx.x;
    const int w = tid >> 5, lane = tid & 31;
    const int qr = lane >> 2, qc = lane & 3;
    // heaviest-first: high qb = most k-tiles, launch first
    const int qb = (int)gridDim.x - 1 - (int)blockIdx.x;
    const int h = blockIdx.y, b = blockIdx.z;
    const int q0 = qb * 64;

    const uint32_t oQl = 17408, oStage = 34816, stSz = 35840;

    const uint32_t lmK = (uint32_t)(lane & 15) * 272 + (uint32_t)(lane >> 4) * 16;
    const uint32_t lmV = (uint32_t)(lane & 15) * 144 + (uint32_t)(lane >> 4) * 16;
    const uint32_t lmQ = (uint32_t)(w * 16) * 272 + lmK;

    // ---- Q tile load (hi/lo) ----
#pragma unroll
    for (int i = 0; i < 16; ++i) {
        int idx = tid + i * 128;
        int mat = idx >> 10, r = (idx >> 4) & 63, v = idx & 15;
        const __half* g = (mat ? Ql : Qh) +
            (size_t)(b * SEQ + q0 + r) * 2048 + h * HEAD_DIM + v * 8;
        CP_ASYNC16(sb + (mat ? oQl : 0u) + r * 272 + v * 16, g);
    }
    CP_COMMIT();

    auto issue = [&](int kt) {
        const int k0 = kt * 64;
        const uint32_t st = sb + oStage + (kt & 1) * stSz;
#pragma unroll
        for (int i = 0; i < 8; ++i) {
            int idx = tid + i * 128;
            int r = idx >> 4, v = idx & 15;
            const __half* g = Kg + (size_t)(b * SEQ + k0 + r) * 2048 + h * HEAD_DIM + v * 8;
            CP_ASYNC16(st + r * 272 + v * 16, g);
        }
#pragma unroll
        for (int i = 0; i < 8; ++i) {
            int idx = tid + i * 128;
            int d = idx >> 3, v = idx & 7;
            const __half* g = VT + (size_t)((b * HEADS + h) * HEAD_DIM + d) * 2048 + k0 + v * 8;
            CP_ASYNC16(st + 17408 + d * 144 + v * 16, g);
        }
        CP_COMMIT();
    };

    float m0 = -1e30f, m1 = -1e30f, l0 = 0.f, l1 = 0.f;
    float acc[16][4];
#pragma unroll
    for (int nt = 0; nt < 16; ++nt)
#pragma unroll
        for (int e = 0; e < 4; ++e) acc[nt][e] = 0.f;

    const int ntk = qb + 1;
    issue(0);

    for (int kt = 0; kt < ntk; ++kt) {
        if (kt + 1 < ntk) { issue(kt + 1); CP_WAIT(1); }
        else              { CP_WAIT(0); }
        __syncthreads();

        const uint32_t st  = sb + oStage + (kt & 1) * stSz;
        const uint32_t aK  = st + lmK;
        const uint32_t aV  = st + 17408 + lmV;
        const uint32_t aQh = sb + lmQ;
        const uint32_t aQl = sb + oQl + lmQ;

        // ---- S = Q K^T (2 terms) ----
        float sfr[8][4];
#pragma unroll
        for (int nt = 0; nt < 8; ++nt)
#pragma unroll
            for (int e = 0; e < 4; ++e) sfr[nt][e] = 0.f;

#pragma unroll
        for (int ks = 0; ks < 8; ++ks) {
            const uint32_t kb = ks * 32;
            uint32_t ah[4], al[4];
            LDSM4(ah[0], ah[1], ah[2], ah[3], aQh + kb);
            LDSM4(al[0], al[1], al[2], al[3], aQl + kb);
#pragma unroll
            for (int np = 0; np < 4; ++np) {
                uint32_t h0, h1, h2, h3;
                LDSM4(h0, h1, h2, h3, aK + (uint32_t)(np * 16) * 272 + kb);
                uint32_t be[2] = { h0, h2 }, bo[2] = { h1, h3 };
                mma16816(sfr[2 * np],     ah, be);
                mma16816(sfr[2 * np],     al, be);
                mma16816(sfr[2 * np + 1], ah, bo);
                mma16816(sfr[2 * np + 1], al, bo);
            }
        }

        // ---- mask (diagonal tile only) + online softmax (exp2 domain) ----
        const int i0 = q0 + w * 16 + qr;
        const int i1 = i0 + 8;
        if (kt == ntk - 1) {
            const int k0 = kt * 64;
#pragma unroll
            for (int nt = 0; nt < 8; ++nt) {
                const int j = k0 + nt * 8 + 2 * qc;
                if (j     > i0) sfr[nt][0] = -1e30f;
                if (j + 1 > i0) sfr[nt][1] = -1e30f;
                if (j     > i1) sfr[nt][2] = -1e30f;
                if (j + 1 > i1) sfr[nt][3] = -1e30f;
            }
        }
        float mx0 = -1e30f, mx1 = -1e30f;
#pragma unroll
        for (int nt = 0; nt < 8; ++nt) {
            mx0 = fmaxf(mx0, fmaxf(sfr[nt][0], sfr[nt][1]));
            mx1 = fmaxf(mx1, fmaxf(sfr[nt][2], sfr[nt][3]));
        }
        mx0 = fmaxf(mx0, __shfl_xor_sync(0xffffffffu, mx0, 1));
        mx0 = fmaxf(mx0, __shfl_xor_sync(0xffffffffu, mx0, 2));
        mx1 = fmaxf(mx1, __shfl_xor_sync(0xffffffffu, mx1, 1));
        mx1 = fmaxf(mx1, __shfl_xor_sync(0xffffffffu, mx1, 2));
        const float mn0 = fmaxf(m0, mx0), mn1 = fmaxf(m1, mx1);
        const float c0 = exp2f(m0 - mn0), c1 = exp2f(m1 - mn1);
        m0 = mn0; m1 = mn1;
        l0 *= c0;  l1 *= c1;

        uint32_t pa[4][4], pl[4][4];
        float rs0 = 0.f, rs1 = 0.f;
#pragma unroll
        for (int nt = 0; nt < 8; ++nt) {
            float p0 = exp2f(sfr[nt][0] - mn0);
            float p1 = exp2f(sfr[nt][1] - mn0);
            float p2 = exp2f(sfr[nt][2] - mn1);
            float p3 = exp2f(sfr[nt][3] - mn1);
            rs0 += p0 + p1; rs1 += p2 + p3;
            uint32_t h01 = pack_hf2(p0, p1);
            uint32_t h23 = pack_hf2(p2, p3);
            __half2 hb01 = *(__half2*)&h01;
            __half2 hb23 = *(__half2*)&h23;
            uint32_t r01 = pack_hf2(p0 - __half2float(__low2half(hb01)),
                                    p1 - __half2float(__high2half(hb01)));
            uint32_t r23 = pack_hf2(p2 - __half2float(__low2half(hb23)),
                                    p3 - __half2float(__high2half(hb23)));
            const int ks = nt >> 1, half = nt & 1;
            if (half == 0) { pa[ks][0] = h01; pa[ks][1] = h23; pl[ks][0] = r01; pl[ks][1] = r23; }
            else           { pa[ks][2] = h01; pa[ks][3] = h23; pl[ks][2] = r01; pl[ks][3] = r23; }
        }
        rs0 += __shfl_xor_sync(0xffffffffu, rs0, 1);
        rs0 += __shfl_xor_sync(0xffffffffu, rs0, 2);
        rs1 += __shfl_xor_sync(0xffffffffu, rs1, 1);
        rs1 += __shfl_xor_sync(0xffffffffu, rs1, 2);
        l0 += rs0; l1 += rs1;

        // rescale only when running max actually changed (corr != exact 1.0)
        if (!__all_sync(0xffffffffu, (c0 == 1.0f) && (c1 == 1.0f))) {
#pragma unroll
            for (int nt = 0; nt < 16; ++nt) {
                acc[nt][0] *= c0; acc[nt][1] *= c0;
                acc[nt][2] *= c1; acc[nt][3] *= c1;
            }
        }

        // ---- O += P V (2 terms) ----
#pragma unroll
        for (int ks = 0; ks < 4; ++ks) {
            const uint32_t kb = ks * 32;
#pragma unroll
            for (int dp = 0; dp < 8; ++dp) {
                uint32_t h0, h1, h2, h3;
                LDSM4(h0, h1, h2, h3, aV + (uint32_t)(dp * 16) * 144 + kb);
                uint32_t be[2] = { h0, h2 }, bo[2] = { h1, h3 };
                mma16816(acc[2 * dp],     pa[ks], be);
                mma16816(acc[2 * dp],     pl[ks], be);
                mma16816(acc[2 * dp + 1], pa[ks], bo);
                mma16816(acc[2 * dp + 1], pl[ks], bo);
            }
        }
        __syncthreads();
    }

    // ---- epilogue: write fp16 single (consumed by single-A Wo GEMM) ----
    const float inv0 = 1.0f / l0, inv1 = 1.0f / l1;
    const size_t r0 = (size_t)(b * SEQ + q0 + w * 16 + qr);
    const size_t r1 = r0 + 8;
#pragma unroll
    for (int nt = 0; nt < 16; ++nt) {
        const int col = h * HEAD_DIM + nt * 8 + 2 * qc;
        *(__half2*)&Ohg[r0 * 2048 + col] =
            __floats2half2_rn(acc[nt][0] * inv0, acc[nt][1] * inv0);
        *(__half2*)&Ohg[r1 * 2048 + col] =
            __floats2half2_rn(acc[nt][2] * inv1, acc[nt][3] * inv1);
    }
}

// ---------------------------------------------------------------------------
extern "C" void kernel_launch(void* const* d_in, const int* in_sizes, int n_in,
                              void* d_out, int out_size)
{
    const float* x    = (const float*)d_in[0];
    const float* Wq   = (const float*)d_in[1];
    const float* Wkvd = (const float*)d_in[2];
    const float* knw  = (const float*)d_in[3];
    const float* Wkvu = (const float*)d_in[4];
    const float* Wo   = (const float*)d_in[5];
    float* out = (float*)d_out;

    float* lat;
    cudaGetSymbolAddress((void**)&lat, g_lat);
    __half *xh,*lath,*aoh,*qh,*ql,*k1,*vrm,*vt;
    __half *WT1,*WkuT,*WoT;
    cudaGetSymbolAddress((void**)&xh, g_xh);
    cudaGetSymbolAddress((void**)&lath, g_lath);
    cudaGetSymbolAddress((void**)&aoh, g_aoh);
    cudaGetSymbolAddress((void**)&qh, g_qh);     cudaGetSymbolAddress((void**)&ql, g_ql);
    cudaGetSymbolAddress((void**)&k1, g_k1);     cudaGetSymbolAddress((void**)&vrm, g_vrm);
    cudaGetSymbolAddress((void**)&vt, g_vt);
    cudaGetSymbolAddress((void**)&WT1, g_WT1);
    cudaGetSymbolAddress((void**)&WkuT, g_WkuT); cudaGetSymbolAddress((void**)&WoT, g_WoT);

    cudaFuncSetAttribute(gemm_mma<1, false>, cudaFuncAttributeMaxDynamicSharedMemorySize, 40960);
    cudaFuncSetAttribute(gemm_mma<2, false>, cudaFuncAttributeMaxDynamicSharedMemorySize, 40960);
    cudaFuncSetAttribute(gemm_mma<0, false>, cudaFuncAttributeMaxDynamicSharedMemorySize, 40960);
    cudaFuncSetAttribute(attn_mma, cudaFuncAttributeMaxDynamicSharedMemorySize, ATT_SMEM);

    // weight conversions: WT1 = [WqT rows 0..2047 ; WkdT rows 2048..2303]
    conv_wt_T<<<dim3(ATTN_DIM / 128, HIDDEN / 32), 256>>>(Wq, WT1, HIDDEN, ATTN_DIM);
    conv_wt_T<<<dim3(KV_RANK / 128, HIDDEN / 32), 256>>>(
        Wkvd, WT1 + (size_t)ATTN_DIM * HIDDEN, HIDDEN, KV_RANK);
    conv_wt_T<<<dim3(2 * ATTN_DIM / 128, KV_RANK / 32), 256>>>(Wkvu, WkuT, KV_RANK, 2 * ATTN_DIM);
    conv_wt_T<<<dim3(HIDDEN / 128, ATTN_DIM / 32), 256>>>(Wo, WoT, ATTN_DIM, HIDDEN);

    // x -> fp16 single
    {
        int n4 = M_ROWS * HIDDEN / 4;
        conv_h<<<(n4 + 255) / 256, 256>>>((const float4*)x, xh, n4);
    }

    // fused q+lat GEMM (single-A): q cols -> qh/ql (scaled to log2 domain)
    gemm_mma<1, false><<<dim3((ATTN_DIM + KV_RANK) / 128, M_ROWS / 128), 256, 40960>>>(
        xh, nullptr, WT1, lat, qh, ql, nullptr,
        M_ROWS, ATTN_DIM + KV_RANK, HIDDEN,
        0.08838834764831845f * 1.4426950408889634f);

    // rmsnorm -> fp16 single
    rmsnorm_kernel<<<M_ROWS, KV_RANK>>>(lat, knw, lath);

    // kv GEMM (single-A): K half -> k1 fp16, V half -> vrm fp16
    gemm_mma<2, false><<<dim3(2 * ATTN_DIM / 128, M_ROWS / 128), 256, 40960>>>(
        lath, nullptr, WkuT, nullptr, k1, nullptr, vrm,
        M_ROWS, 2 * ATTN_DIM, KV_RANK, 1.0f);

    // V transpose (fp16 -> fp16)
    conv_vt_h<<<dim3(SEQ / 32, (HEADS * HEAD_DIM) / 32, BATCH), 256>>>(vrm, vt);

    // tensor-core attention (Q tile 64, 2 CTAs/SM, heaviest-first)
    attn_mma<<<dim3(SEQ / 64, HEADS, BATCH), 128, ATT_SMEM>>>(
        qh, ql, k1, vt, aoh);

    // out = ao @ Wo (fp32 out, single-A term)
    gemm_mma<0, false><<<dim3(HIDDEN / 128, M_ROWS / 128), 256, 40960>>>(
        aoh, nullptr, WoT, out, nullptr, nullptr, nullptr,
        M_ROWS, HIDDEN, ATTN_DIM, 1.0f);
}